// round 16
// baseline (speedup 1.0000x reference)
#include <cuda_runtime.h>
#include <math.h>

#define M_ROWS  131072
#define N_CODES 2048
#define NH      1024          // codes per CTA (N-split half)
#define K_DIM   256
#define KW      64            // int words per row (4 int8 per word)
#define BM 128
#define BN 64
#define TM 8
#define TN 2
#define PITCHA 132            // A smem pitch (rows)
#define PITCHB 68             // B smem pitch (codes)
#define MW    64              // mask words per row (2048 bits)

#define OFF_Q    1
#define OFF_PERP 33554433
#define OFF_ENC  33554434

#define EPI_BLOCKS (M_ROWS / 8)

#define MARGIN  2e-3f
#define S_E     260096.0f     // 127 * 2048 (exact in fp32)

// ---- phase1 dynamic smem (ints) ----
#define A_INTS   (KW * PITCHA)              // 8448
#define B_INTS   (KW * PITCHB)              // 4352
#define SM_B0    A_INTS
#define SM_B1    (A_INTS + B_INTS)
#define SM_RMIN  (A_INTS + 2 * B_INTS)      // 128 floats
#define SM_M2S   (SM_RMIN + 128)            // 128 floats
#define SM_TOTAL ((SM_M2S + 128) * 4)

// -------- device scratch (no allocations allowed) --------
__device__ int      g_indices[M_ROWS];
__device__ int      g_hist[N_CODES];
__device__ float    g_cbnorm[N_CODES];
__device__ float    g_cbn4[N_CODES];   // cbnorm + 4 (phase1 fast path)
__device__ float    g_xnorm[M_ROWS];
__device__ float    g_xsx[M_ROWS];     // 127/max|x| pack scale
__device__ float    g_xdq[M_ROWS];     // max|x|/(127*S_E) dequant factor
__device__ double   g_part[EPI_BLOCKS];
__device__ int      g_cbi[N_CODES * KW];    // int8-packed codebook (512 KB)
__device__ int      g_xi8[M_ROWS * KW];     // int8-packed inputs  (32 MB)
__device__ unsigned g_mask[M_ROWS * MW];    // candidate bitmask    (32 MB)

// ============================================================
// Kernel 1: exact codebook norms (reference fp32 rounding emulation)
// + int8 codebook pack + zero histogram. One thread per code.
// ============================================================
__global__ void vq_init(const float* __restrict__ CB) {
    int gid = blockIdx.x * blockDim.x + threadIdx.x;
    if (gid >= N_CODES) return;
    const float* row = CB + (long)gid * K_DIM;
    float s = 0.f;
    for (int w = 0; w < KW; w++) {
        int pack = 0;
#pragma unroll
        for (int b = 0; b < 4; b++) {
            float v = row[w * 4 + b];
            s = __fadd_rn(s, __fmul_rn(v, v));   // no FMA contraction
            int q = __float2int_rn(v * S_E);     // |e|<=1/2048 -> |q|<=127
            pack |= (q & 0xFF) << (b * 8);
        }
        g_cbi[gid * KW + w] = pack;
    }
    g_cbnorm[gid] = s;
    g_cbn4[gid]   = s + 4.0f;
    g_hist[gid] = 0;
}

// ============================================================
// Kernel 1b: per-row ||x||^2 exact scalar-sequential emulation
// + per-row max|x| -> pack/dequant scales.
// ============================================================
__global__ void vq_xnorm(const float* __restrict__ X) {
    __shared__ float sh[256][33];
    const int tid = threadIdx.x;
    const long r0 = (long)blockIdx.x * 256;
    float acc = 0.f;
    float mx = 1e-20f;
    for (int c0 = 0; c0 < K_DIM; c0 += 32) {
        for (int idx = tid; idx < 256 * 32; idx += 256) {
            int row = idx >> 5, col = idx & 31;
            sh[row][col] = X[(r0 + row) * K_DIM + c0 + col];
        }
        __syncthreads();
#pragma unroll
        for (int c = 0; c < 32; c++) {
            float v = sh[tid][c];
            acc = __fadd_rn(acc, __fmul_rn(v, v));
            mx = fmaxf(mx, fabsf(v));
        }
        __syncthreads();
    }
    g_xnorm[r0 + tid] = acc;
    g_xsx[r0 + tid] = 127.0f / mx;
    g_xdq[r0 + tid] = mx * (1.0f / S_E / 127.0f);
}

// ============================================================
// Kernel 1c: pack X to int8 (one int word per thread) + zero the
// candidate mask (same index space: MW == KW words per row).
// ============================================================
__global__ void vq_xpack(const float* __restrict__ X) {
    const int gid = blockIdx.x * blockDim.x + threadIdx.x;   // word index
    const int row = gid >> 6;
    const float sx = g_xsx[row];
    float4 v = *(const float4*)(X + (long)gid * 4);
    int q0 = __float2int_rn(v.x * sx);
    int q1 = __float2int_rn(v.y * sx);
    int q2 = __float2int_rn(v.z * sx);
    int q3 = __float2int_rn(v.w * sx);
    g_xi8[gid] = (q0 & 0xFF) | ((q1 & 0xFF) << 8) | ((q2 & 0xFF) << 16)
               | (q3 << 24);
    g_mask[gid] = 0u;
}

// ============================================================
// Tile loaders into [w * pitch + row] layout.
// A: 128 rows (512 thr: row=tid>>2, 4 int4 each).
// B: 64 codes (512 thr: row=tid>>3, 2 int4 each).
// ============================================================
__device__ __forceinline__ void load_tileA(const int* __restrict__ gsrc,
                                           int* __restrict__ dst, int tid) {
    const int row = tid >> 2, w0 = (tid & 3) * 16;
    const int4* src = (const int4*)(gsrc + row * KW + w0);
#pragma unroll
    for (int q = 0; q < 4; q++) {
        int4 v = src[q];
        const int w = w0 + q * 4;
        dst[(w + 0) * PITCHA + row] = v.x;
        dst[(w + 1) * PITCHA + row] = v.y;
        dst[(w + 2) * PITCHA + row] = v.z;
        dst[(w + 3) * PITCHA + row] = v.w;
    }
}
__device__ __forceinline__ void load_tileB(const int* __restrict__ gsrc,
                                           int* __restrict__ dst, int tid) {
    const int row = tid >> 3, w0 = (tid & 7) * 8;
    const int4* src = (const int4*)(gsrc + row * KW + w0);
#pragma unroll
    for (int q = 0; q < 2; q++) {
        int4 v = src[q];
        const int w = w0 + q * 4;
        dst[(w + 0) * PITCHB + row] = v.x;
        dst[(w + 1) * PITCHB + row] = v.y;
        dst[(w + 2) * PITCHB + row] = v.z;
        dst[(w + 3) * PITCHB + row] = v.w;
    }
}

// ============================================================
// Kernel 2 (phase 1): int8 DP4A GEMM + candidate filter.
// N-SPLIT x2: CTA = (rowblock, half). 512 thr, 3 CTAs/SM target
// (rowmin/m2s in smem to stay under the 42-reg cap).
// Warp ty owns rows ty*8..+7; lane owns 2 codes of a 64-code tile.
// Per warp-w: 2 bcast LDS.128 (A) + 1 LDS.64 (B) + 16 DP4A
// -> DP4A-pipe-bound (LDS ~50%). Bitmask RED.OR candidate store.
// Half-local rowmin threshold >= global one -> superset (exact
// phase2 rescore keeps indices bit-identical).
// ============================================================
__global__ void __launch_bounds__(512, 3)
vq_phase1() {
    extern __shared__ int sm[];
    int*   As   = sm;
    int*   Bs0  = sm + SM_B0;
    int*   Bs1  = sm + SM_B1;
    float* rmin = (float*)(sm + SM_RMIN);
    float* m2s  = (float*)(sm + SM_M2S);

    const int tid = threadIdx.x;
    const int tx = tid & 31;            // lane: 2 codes
    const int ty = tid >> 5;            // warp: 8 rows (0..15)
    const long row0 = (long)(blockIdx.x >> 1) * BM;
    const int cbase = (int)(blockIdx.x & 1) * NH;
    const int ty8 = ty * 8, tx2 = tx * 2;

    if (tid < BM) {
        rmin[tid] = INFINITY;
        m2s[tid] = -2.0f * g_xdq[row0 + tid];
    }
    load_tileA(g_xi8 + row0 * KW, As, tid);
    load_tileB(g_cbi + (long)cbase * KW, Bs0, tid);
    __syncthreads();

    for (int nt = 0; nt < NH / BN; ++nt) {
        int* cur = (nt & 1) ? Bs1 : Bs0;
        int* nxt = (nt & 1) ? Bs0 : Bs1;
        if (nt + 1 < NH / BN)
            load_tileB(g_cbi + (long)(cbase + (nt + 1) * BN) * KW, nxt, tid);

        int acc[TM][TN];
#pragma unroll
        for (int i = 0; i < TM; i++)
#pragma unroll
            for (int j = 0; j < TN; j++) acc[i][j] = 0;

#pragma unroll 8
        for (int w = 0; w < KW; w++) {
            int4 a0 = *(const int4*)(As + w * PITCHA + ty8);       // bcast
            int4 a1 = *(const int4*)(As + w * PITCHA + ty8 + 4);   // bcast
            int2 b  = *(const int2*)(cur + w * PITCHB + tx2);
            acc[0][0] = __dp4a(a0.x, b.x, acc[0][0]);
            acc[0][1] = __dp4a(a0.x, b.y, acc[0][1]);
            acc[1][0] = __dp4a(a0.y, b.x, acc[1][0]);
            acc[1][1] = __dp4a(a0.y, b.y, acc[1][1]);
            acc[2][0] = __dp4a(a0.z, b.x, acc[2][0]);
            acc[2][1] = __dp4a(a0.z, b.y, acc[2][1]);
            acc[3][0] = __dp4a(a0.w, b.x, acc[3][0]);
            acc[3][1] = __dp4a(a0.w, b.y, acc[3][1]);
            acc[4][0] = __dp4a(a1.x, b.x, acc[4][0]);
            acc[4][1] = __dp4a(a1.x, b.y, acc[4][1]);
            acc[5][0] = __dp4a(a1.y, b.x, acc[5][0]);
            acc[5][1] = __dp4a(a1.y, b.y, acc[5][1]);
            acc[6][0] = __dp4a(a1.z, b.x, acc[6][0]);
            acc[6][1] = __dp4a(a1.z, b.y, acc[6][1]);
            acc[7][0] = __dp4a(a1.w, b.x, acc[7][0]);
            acc[7][1] = __dp4a(a1.w, b.y, acc[7][1]);
        }

        float2 cb = *(const float2*)(g_cbn4 + cbase + nt * BN + tx2);

#pragma unroll
        for (int i = 0; i < TM; i++) {
            const float m2 = m2s[ty8 + i];                // bcast LDS
            float s0 = fmaf(m2, (float)acc[i][0], cb.x);
            float s1 = fmaf(m2, (float)acc[i][1], cb.y);
            float tmin = fminf(s0, s1);
            unsigned r = __reduce_min_sync(0xffffffffu, __float_as_uint(tmin));
            float wmin = __uint_as_float(r);
            float cur_min;
            if (tx == 0) {                                // lane 0 owns RMW
                cur_min = fminf(rmin[ty8 + i], wmin);
                rmin[ty8 + i] = cur_min;
            }
            cur_min = __shfl_sync(0xffffffffu, cur_min, 0);
            const float thr = cur_min + MARGIN;
            if (wmin <= thr) {                            // warp-uniform guard
                const long grow = row0 + ty8 + i;
                if (s0 <= thr) {
                    int code = cbase + nt * BN + tx2;
                    atomicOr(&g_mask[grow * MW + (code >> 5)], 1u << (code & 31));
                }
                if (s1 <= thr) {
                    int code = cbase + nt * BN + tx2 + 1;
                    atomicOr(&g_mask[grow * MW + (code >> 5)], 1u << (code & 31));
                }
            }
        }
        __syncthreads();
    }
}

// ============================================================
// Kernel 3 (phase 2): exact rescoring from the bitmask (reference
// fp32 rounding chain: sequential fmaf k ascending;
// d = fl(fl(xn+cn) - fl(2m))), lowest-index tie-break.
// One warp per row; lane l owns mask words l and 32+l.
// total==1 -> that candidate IS the argmin (superset guarantee).
// ============================================================
__device__ __forceinline__ float exact_dist(const float* __restrict__ xr,
                                            const float* __restrict__ er,
                                            float xn, float cn) {
    float m = 0.f;
#pragma unroll 8
    for (int k = 0; k < K_DIM; k += 4) {
        float4 xv = *(const float4*)(xr + k);
        float4 ev = *(const float4*)(er + k);
        m = fmaf(xv.x, ev.x, m);
        m = fmaf(xv.y, ev.y, m);
        m = fmaf(xv.z, ev.z, m);
        m = fmaf(xv.w, ev.w, m);
    }
    return __fsub_rn(__fadd_rn(xn, cn), __fmul_rn(2.f, m));
}

__global__ void vq_phase2(const float* __restrict__ X,
                          const float* __restrict__ CB) {
    const int wid  = threadIdx.x >> 5;
    const int lane = threadIdx.x & 31;
    const long row = (long)blockIdx.x * 8 + wid;

    unsigned m0 = g_mask[row * MW + lane];
    unsigned m1 = g_mask[row * MW + 32 + lane];
    const int cnt = __popc(m0) + __popc(m1);
    const int total = __reduce_add_sync(0xffffffffu, cnt);

    if (total == 1) {
        if (cnt) {
            int code = m0 ? (lane * 32 + __ffs(m0) - 1)
                          : (1024 + lane * 32 + __ffs(m1) - 1);
            g_indices[row] = code;
        }
        return;
    }

    const float xn = g_xnorm[row];
    const float* xr = X + row * K_DIM;

    unsigned long long key = 0xFFFFFFFFFFFFFFFFULL;
    while (m0) {
        int b = __ffs(m0) - 1; m0 &= m0 - 1;
        int code = lane * 32 + b;
        float d = exact_dist(xr, CB + (long)code * K_DIM, xn, g_cbnorm[code]);
        unsigned long long k2 =
            ((unsigned long long)__float_as_uint(d) << 32) | (unsigned)code;
        if (k2 < key) key = k2;
    }
    while (m1) {
        int b = __ffs(m1) - 1; m1 &= m1 - 1;
        int code = 1024 + lane * 32 + b;
        float d = exact_dist(xr, CB + (long)code * K_DIM, xn, g_cbnorm[code]);
        unsigned long long k2 =
            ((unsigned long long)__float_as_uint(d) << 32) | (unsigned)code;
        if (k2 < key) key = k2;
    }
#pragma unroll
    for (int o = 16; o; o >>= 1) {
        unsigned long long other = __shfl_xor_sync(0xffffffffu, key, o);
        if (other < key) key = other;
    }
    if (lane == 0) g_indices[row] = (int)(key & 0xFFFFFFFFu);
}

// ============================================================
// Kernel 4: epilogue. One warp per row. quantized_st = fl(x + fl(q-x)),
// one-hot row in one pass, histogram, deterministic SSE partials.
// ============================================================
__global__ void vq_epilogue(const float* __restrict__ X,
                            const float* __restrict__ CB,
                            float* __restrict__ out) {
    __shared__ float warp_sse[8];
    const int wid  = threadIdx.x >> 5;
    const int lane = threadIdx.x & 31;
    const long row = (long)blockIdx.x * 8 + wid;
    const int idx = g_indices[row];

    const float4* xr = reinterpret_cast<const float4*>(X + row * K_DIM);
    const float4* cr = reinterpret_cast<const float4*>(CB + (long)idx * K_DIM);
    float* q = out + OFF_Q + row * K_DIM;

    float sse = 0.f;
#pragma unroll
    for (int t = 0; t < 2; t++) {
        int c4 = lane + 32 * t;
        float4 xv = xr[c4];
        float4 cv = cr[c4];
        float d0 = __fsub_rn(cv.x, xv.x);
        float d1 = __fsub_rn(cv.y, xv.y);
        float d2 = __fsub_rn(cv.z, xv.z);
        float d3 = __fsub_rn(cv.w, xv.w);
        q[c4 * 4 + 0] = __fadd_rn(xv.x, d0);
        q[c4 * 4 + 1] = __fadd_rn(xv.y, d1);
        q[c4 * 4 + 2] = __fadd_rn(xv.z, d2);
        q[c4 * 4 + 3] = __fadd_rn(xv.w, d3);
        sse += d0 * d0 + d1 * d1 + d2 * d2 + d3 * d3;
    }

    float2* enc = reinterpret_cast<float2*>(out + OFF_ENC + row * (long)N_CODES);
    const int hot_chunk = idx >> 1;
#pragma unroll
    for (int t = 0; t < 32; t++) {
        int c = lane + 32 * t;
        float2 v = make_float2(0.f, 0.f);
        if (c == hot_chunk) { if (idx & 1) v.y = 1.f; else v.x = 1.f; }
        enc[c] = v;
    }

#pragma unroll
    for (int o = 16; o; o >>= 1) sse += __shfl_xor_sync(0xffffffffu, sse, o);
    if (lane == 0) {
        atomicAdd(&g_hist[idx], 1);
        warp_sse[wid] = sse;
    }
    __syncthreads();
    if (threadIdx.x == 0) {
        double s = 0.0;
        for (int w = 0; w < 8; w++) s += (double)warp_sse[w];
        g_part[blockIdx.x] = s;
    }
}

// ============================================================
// Kernel 5: finalize loss + perplexity (1 block, deterministic)
// ============================================================
__global__ void vq_finalize(float* __restrict__ out) {
    __shared__ double sh[256];
    __shared__ double sh2[256];
    const int tid = threadIdx.x;

    double s = 0.0;
    for (int i = tid; i < EPI_BLOCKS; i += 256) s += g_part[i];
    sh[tid] = s;

    double ent = 0.0;
    for (int i = tid; i < N_CODES; i += 256) {
        double p = (double)g_hist[i] * (1.0 / (double)M_ROWS);
        ent -= p * log(p + 1e-10);
    }
    sh2[tid] = ent;
    __syncthreads();

    for (int st = 128; st; st >>= 1) {
        if (tid < st) { sh[tid] += sh[tid + st]; sh2[tid] += sh2[tid + st]; }
        __syncthreads();
    }
    if (tid == 0) {
        double mse = sh[0] / ((double)M_ROWS * (double)K_DIM);
        out[0]        = (float)(1.25 * mse);
        out[OFF_PERP] = (float)exp(sh2[0]);
    }
}

// ============================================================
extern "C" void kernel_launch(void* const* d_in, const int* in_sizes, int n_in,
                              void* d_out, int out_size) {
    const float* X  = (const float*)d_in[0];
    const float* CB = (const float*)d_in[1];
    float* out = (float*)d_out;

    cudaFuncSetAttribute(vq_phase1,
                         cudaFuncAttributeMaxDynamicSharedMemorySize, SM_TOTAL);

    vq_init<<<8, 256>>>(CB);
    vq_xnorm<<<M_ROWS / 256, 256>>>(X);
    vq_xpack<<<M_ROWS * KW / 256, 256>>>(X);
    vq_phase1<<<(M_ROWS / BM) * 2, 512, SM_TOTAL>>>();
    vq_phase2<<<M_ROWS / 8, 256>>>(X, CB);
    vq_epilogue<<<EPI_BLOCKS, 256>>>(X, CB, out);
    vq_finalize<<<1, 256>>>(out);
}

// round 17
// speedup vs baseline: 1.2549x; 1.2549x over previous
#include <cuda_runtime.h>
#include <math.h>

#define M_ROWS  131072
#define N_CODES 2048
#define K_DIM   256
#define KW      64            // int words per row (4 int8 per word)
#define BM 128
#define BN 128
#define TM 8
#define TN 4
#define PITCHW 132            // padded ints per k-word row in smem
#define MW      64            // mask words per row (2048 bits)

#define OFF_Q    1
#define OFF_PERP 33554433
#define OFF_ENC  33554434

#define EPI_BLOCKS (M_ROWS / 8)

#define MARGIN  2e-3f
#define S_E     260096.0f     // 127 * 2048 (exact in fp32)

// ---- phase1 dynamic smem layout (bytes) ----
#define SM_A     0            // 64 x 132 ints  (33792)
#define SM_B0    33792
#define SM_B1    67584
#define SM_CBN   101376       // 2048 floats (cbnorm + 4)
#define SM_M2S   109568       // 128 floats (-2*dq per row)
#define SM_TOTAL 110080

// -------- device scratch (no allocations allowed) --------
__device__ int      g_hist[N_CODES];
__device__ float    g_cbnorm[N_CODES];
__device__ float    g_xnorm[M_ROWS];
__device__ float    g_xsx[M_ROWS];     // 127/max|x| pack scale
__device__ float    g_xdq[M_ROWS];     // max|x|/(127*S_E) dequant factor
__device__ double   g_part[EPI_BLOCKS];
__device__ int      g_cbi[N_CODES * KW];    // int8-packed codebook (512 KB)
__device__ int      g_xi8[M_ROWS * KW];     // int8-packed inputs  (32 MB)
__device__ unsigned g_mask[M_ROWS * MW];    // candidate bitmask    (32 MB)

// ============================================================
// Kernel 1: exact codebook norms (reference fp32 rounding emulation)
// + int8 codebook pack + zero histogram. Coalesced via smem staging:
// block = 128 codes, thread owns one code, data staged 32 cols at a
// time (xnorm pattern). Grid 16 x 128.
// ============================================================
__global__ void vq_init(const float* __restrict__ CB) {
    __shared__ float sh[128][33];
    const int tid = threadIdx.x;
    const long c0 = (long)blockIdx.x * 128;
    float s = 0.f;
    for (int k0 = 0; k0 < K_DIM; k0 += 32) {
        for (int idx = tid; idx < 128 * 32; idx += 128) {
            int row = idx >> 5, col = idx & 31;
            sh[row][col] = CB[(c0 + row) * K_DIM + k0 + col];
        }
        __syncthreads();
#pragma unroll
        for (int w = 0; w < 8; w++) {
            int pack = 0;
#pragma unroll
            for (int b = 0; b < 4; b++) {
                float v = sh[tid][w * 4 + b];
                s = __fadd_rn(s, __fmul_rn(v, v));   // no FMA contraction
                int q = __float2int_rn(v * S_E);     // |e|<=1/2048 -> |q|<=127
                pack |= (q & 0xFF) << (b * 8);
            }
            g_cbi[(c0 + tid) * KW + (k0 >> 2) + w] = pack;
        }
        __syncthreads();
    }
    g_cbnorm[c0 + tid] = s;
    if (blockIdx.x < 16) {
        int h = blockIdx.x * 128 + tid;
        g_hist[h] = 0;
    }
}

// ============================================================
// Kernel 1b: per-row ||x||^2 exact scalar-sequential emulation
// + per-row max|x| -> pack/dequant scales.
// ============================================================
__global__ void vq_xnorm(const float* __restrict__ X) {
    __shared__ float sh[256][33];
    const int tid = threadIdx.x;
    const long r0 = (long)blockIdx.x * 256;
    float acc = 0.f;
    float mx = 1e-20f;
    for (int c0 = 0; c0 < K_DIM; c0 += 32) {
        for (int idx = tid; idx < 256 * 32; idx += 256) {
            int row = idx >> 5, col = idx & 31;
            sh[row][col] = X[(r0 + row) * K_DIM + c0 + col];
        }
        __syncthreads();
#pragma unroll
        for (int c = 0; c < 32; c++) {
            float v = sh[tid][c];
            acc = __fadd_rn(acc, __fmul_rn(v, v));
            mx = fmaxf(mx, fabsf(v));
        }
        __syncthreads();
    }
    g_xnorm[r0 + tid] = acc;
    g_xsx[r0 + tid] = 127.0f / mx;
    g_xdq[r0 + tid] = mx * (1.0f / S_E / 127.0f);
}

// ============================================================
// Kernel 1c: pack X to int8 (one int word per thread) + zero the
// candidate mask (same index space: MW == KW words per row).
// ============================================================
__global__ void vq_xpack(const float* __restrict__ X) {
    const int gid = blockIdx.x * blockDim.x + threadIdx.x;   // word index
    const int row = gid >> 6;
    const float sx = g_xsx[row];
    float4 v = *(const float4*)(X + (long)gid * 4);
    int q0 = __float2int_rn(v.x * sx);
    int q1 = __float2int_rn(v.y * sx);
    int q2 = __float2int_rn(v.z * sx);
    int q3 = __float2int_rn(v.w * sx);
    g_xi8[gid] = (q0 & 0xFF) | ((q1 & 0xFF) << 8) | ((q2 & 0xFF) << 16)
               | (q3 << 24);
    g_mask[gid] = 0u;
}

// ============================================================
// load a 128-row x 64-word int8 tile into smem [w*PITCHW + row]
// (512-thread version: each thread 16 words of one row)
// ============================================================
__device__ __forceinline__ void load_tile(const int* __restrict__ gsrc,
                                          int* __restrict__ dst, int tid) {
    const int row = tid >> 2, w0 = (tid & 3) * 16;
    const int4* src = (const int4*)(gsrc + row * KW + w0);
#pragma unroll
    for (int q = 0; q < 4; q++) {
        int4 v = src[q];
        const int w = w0 + q * 4;
        dst[(w + 0) * PITCHW + row] = v.x;
        dst[(w + 1) * PITCHW + row] = v.y;
        dst[(w + 2) * PITCHW + row] = v.z;
        dst[(w + 3) * PITCHW + row] = v.w;
    }
}

// ============================================================
// Kernel 2 (phase 1): int8 DP4A GEMM + candidate filter (R13 form,
// byte-identical — measured best; DP4A pipe-floor bound).
// ============================================================
__global__ void __launch_bounds__(512, 2)
vq_phase1() {
    extern __shared__ unsigned char smraw[];
    int*   As   = (int*)(smraw + SM_A);
    int*   Bs0  = (int*)(smraw + SM_B0);
    int*   Bs1  = (int*)(smraw + SM_B1);
    float* cbn4 = (float*)(smraw + SM_CBN);
    float* m2s  = (float*)(smraw + SM_M2S);

    const int tid = threadIdx.x;
    const int tx = tid & 31;            // code direction (4 codes each)
    const int ty = tid >> 5;            // warp id = row group (8 rows)
    const long row0 = (long)blockIdx.x * BM;
    const int ty8 = ty * 8, tx4 = tx * 4;

    for (int i = tid; i < N_CODES; i += 512) cbn4[i] = g_cbnorm[i] + 4.0f;
    if (tid < BM) m2s[tid] = -2.0f * g_xdq[row0 + tid];

    load_tile(g_xi8 + row0 * KW, As, tid);
    load_tile(g_cbi, Bs0, tid);
    __syncthreads();

    float rowmin[TM];
#pragma unroll
    for (int i = 0; i < TM; i++) rowmin[i] = INFINITY;

    float m2r[TM];
#pragma unroll
    for (int i = 0; i < TM; i++) m2r[i] = m2s[ty8 + i];

    for (int nt = 0; nt < N_CODES / BN; ++nt) {
        int* cur = (nt & 1) ? Bs1 : Bs0;
        int* nxt = (nt & 1) ? Bs0 : Bs1;
        if (nt + 1 < N_CODES / BN)
            load_tile(g_cbi + (nt + 1) * BN * KW, nxt, tid);

        int acc[TM][TN];
#pragma unroll
        for (int i = 0; i < TM; i++)
#pragma unroll
            for (int j = 0; j < TN; j++) acc[i][j] = 0;

#pragma unroll 4
        for (int w = 0; w < KW; w++) {
            int a[TM], b[TN];
            const int4* pa = (const int4*)(As + w * PITCHW + ty8);
            int4 t0 = pa[0], t1 = pa[1];           // broadcast (warp-uniform)
            a[0] = t0.x; a[1] = t0.y; a[2] = t0.z; a[3] = t0.w;
            a[4] = t1.x; a[5] = t1.y; a[6] = t1.z; a[7] = t1.w;
            int4 u = *(const int4*)(cur + w * PITCHW + tx4);
            b[0] = u.x; b[1] = u.y; b[2] = u.z; b[3] = u.w;
#pragma unroll
            for (int i = 0; i < TM; i++)
#pragma unroll
                for (int j = 0; j < TN; j++)
                    acc[i][j] = __dp4a(a[i], b[j], acc[i][j]);
        }

        float4 cbv4 = *(const float4*)(cbn4 + nt * BN + tx4);
        const float cbv[TN] = {cbv4.x, cbv4.y, cbv4.z, cbv4.w};

        // pass 1: running per-row min via warp REDUX (no atomics/sync)
#pragma unroll
        for (int i = 0; i < TM; i++) {
            float tmin = INFINITY;
#pragma unroll
            for (int j = 0; j < TN; j++) {
                float s4 = fmaf(m2r[i], (float)acc[i][j], cbv[j]);
                tmin = fminf(tmin, s4);
            }
            unsigned r = __reduce_min_sync(0xffffffffu, __float_as_uint(tmin));
            rowmin[i] = fminf(rowmin[i], __uint_as_float(r));
        }

        // pass 2: candidate collection -> bitmask (RED.OR, no return)
#pragma unroll
        for (int i = 0; i < TM; i++) {
            const float thr = rowmin[i] + MARGIN;
            const long grow = row0 + ty8 + i;
#pragma unroll
            for (int j = 0; j < TN; j++) {
                float s4 = fmaf(m2r[i], (float)acc[i][j], cbv[j]);
                if (s4 <= thr) {
                    int code = nt * BN + tx4 + j;
                    atomicOr(&g_mask[grow * MW + (code >> 5)],
                             1u << (code & 31));
                }
            }
        }
        __syncthreads();
    }
}

// ============================================================
// Kernel 3: fused phase2 + epilogue. One warp per row.
//  - argmin from bitmask: total==1 fast path (superset guarantee),
//    else exact rescoring (reference fp32 rounding chain: sequential
//    fmaf k ascending; d = fl(fl(xn+cn) - fl(2m))), lowest-index ties.
//  - quantized_st = fl(x + fl(q-x)), one-hot row, histogram,
//    deterministic SSE partials.
// ============================================================
__device__ __forceinline__ float exact_dist(const float* __restrict__ xr,
                                            const float* __restrict__ er,
                                            float xn, float cn) {
    float m = 0.f;
#pragma unroll 8
    for (int k = 0; k < K_DIM; k += 4) {
        float4 xv = *(const float4*)(xr + k);
        float4 ev = *(const float4*)(er + k);
        m = fmaf(xv.x, ev.x, m);
        m = fmaf(xv.y, ev.y, m);
        m = fmaf(xv.z, ev.z, m);
        m = fmaf(xv.w, ev.w, m);
    }
    return __fsub_rn(__fadd_rn(xn, cn), __fmul_rn(2.f, m));
}

__global__ void vq_epilogue(const float* __restrict__ X,
                            const float* __restrict__ CB,
                            float* __restrict__ out) {
    __shared__ float warp_sse[8];
    const int wid  = threadIdx.x >> 5;
    const int lane = threadIdx.x & 31;
    const long row = (long)blockIdx.x * 8 + wid;

    // ---- inline phase2: argmin from bitmask ----
    unsigned m0 = g_mask[row * MW + lane];
    unsigned m1 = g_mask[row * MW + 32 + lane];
    const int cnt = __popc(m0) + __popc(m1);
    const int total = __reduce_add_sync(0xffffffffu, cnt);

    int idx;
    if (total == 1) {
        int c = -1;
        if (cnt)
            c = m0 ? (lane * 32 + __ffs(m0) - 1)
                   : (1024 + lane * 32 + __ffs(m1) - 1);
        idx = __reduce_max_sync(0xffffffffu, c);
    } else {
        const float xn = g_xnorm[row];
        const float* xr = X + row * K_DIM;
        unsigned long long key = 0xFFFFFFFFFFFFFFFFULL;
        while (m0) {
            int b = __ffs(m0) - 1; m0 &= m0 - 1;
            int code = lane * 32 + b;
            float d = exact_dist(xr, CB + (long)code * K_DIM, xn, g_cbnorm[code]);
            unsigned long long k2 =
                ((unsigned long long)__float_as_uint(d) << 32) | (unsigned)code;
            if (k2 < key) key = k2;
        }
        while (m1) {
            int b = __ffs(m1) - 1; m1 &= m1 - 1;
            int code = 1024 + lane * 32 + b;
            float d = exact_dist(xr, CB + (long)code * K_DIM, xn, g_cbnorm[code]);
            unsigned long long k2 =
                ((unsigned long long)__float_as_uint(d) << 32) | (unsigned)code;
            if (k2 < key) key = k2;
        }
#pragma unroll
        for (int o = 16; o; o >>= 1) {
            unsigned long long other = __shfl_xor_sync(0xffffffffu, key, o);
            if (other < key) key = other;
        }
        idx = (int)(key & 0xFFFFFFFFu);
    }

    // ---- epilogue ----
    const float4* xr4 = reinterpret_cast<const float4*>(X + row * K_DIM);
    const float4* cr4 = reinterpret_cast<const float4*>(CB + (long)idx * K_DIM);
    float* q = out + OFF_Q + row * K_DIM;

    float sse = 0.f;
#pragma unroll
    for (int t = 0; t < 2; t++) {
        int c4 = lane + 32 * t;
        float4 xv = xr4[c4];
        float4 cv = cr4[c4];
        float d0 = __fsub_rn(cv.x, xv.x);
        float d1 = __fsub_rn(cv.y, xv.y);
        float d2 = __fsub_rn(cv.z, xv.z);
        float d3 = __fsub_rn(cv.w, xv.w);
        q[c4 * 4 + 0] = __fadd_rn(xv.x, d0);
        q[c4 * 4 + 1] = __fadd_rn(xv.y, d1);
        q[c4 * 4 + 2] = __fadd_rn(xv.z, d2);
        q[c4 * 4 + 3] = __fadd_rn(xv.w, d3);
        sse += d0 * d0 + d1 * d1 + d2 * d2 + d3 * d3;
    }

    float2* enc = reinterpret_cast<float2*>(out + OFF_ENC + row * (long)N_CODES);
    const int hot_chunk = idx >> 1;
#pragma unroll
    for (int t = 0; t < 32; t++) {
        int c = lane + 32 * t;
        float2 v = make_float2(0.f, 0.f);
        if (c == hot_chunk) { if (idx & 1) v.y = 1.f; else v.x = 1.f; }
        enc[c] = v;
    }

#pragma unroll
    for (int o = 16; o; o >>= 1) sse += __shfl_xor_sync(0xffffffffu, sse, o);
    if (lane == 0) {
        atomicAdd(&g_hist[idx], 1);
        warp_sse[wid] = sse;
    }
    __syncthreads();
    if (threadIdx.x == 0) {
        double s = 0.0;
        for (int w = 0; w < 8; w++) s += (double)warp_sse[w];
        g_part[blockIdx.x] = s;
    }
}

// ============================================================
// Kernel 4: finalize loss + perplexity (1 block, deterministic)
// ============================================================
__global__ void vq_finalize(float* __restrict__ out) {
    __shared__ double sh[256];
    __shared__ double sh2[256];
    const int tid = threadIdx.x;

    double s = 0.0;
    for (int i = tid; i < EPI_BLOCKS; i += 256) s += g_part[i];
    sh[tid] = s;

    double ent = 0.0;
    for (int i = tid; i < N_CODES; i += 256) {
        double p = (double)g_hist[i] * (1.0 / (double)M_ROWS);
        ent -= p * log(p + 1e-10);
    }
    sh2[tid] = ent;
    __syncthreads();

    for (int st = 128; st; st >>= 1) {
        if (tid < st) { sh[tid] += sh[tid + st]; sh2[tid] += sh2[tid + st]; }
        __syncthreads();
    }
    if (tid == 0) {
        double mse = sh[0] / ((double)M_ROWS * (double)K_DIM);
        out[0]        = (float)(1.25 * mse);
        out[OFF_PERP] = (float)exp(sh2[0]);
    }
}

// ============================================================
extern "C" void kernel_launch(void* const* d_in, const int* in_sizes, int n_in,
                              void* d_out, int out_size) {
    const float* X  = (const float*)d_in[0];
    const float* CB = (const float*)d_in[1];
    float* out = (float*)d_out;

    cudaFuncSetAttribute(vq_phase1,
                         cudaFuncAttributeMaxDynamicSharedMemorySize, SM_TOTAL);

    vq_init<<<N_CODES / 128, 128>>>(CB);
    vq_xnorm<<<M_ROWS / 256, 256>>>(X);
    vq_xpack<<<M_ROWS * KW / 256, 256>>>(X);
    vq_phase1<<<M_ROWS / BM, 512, SM_TOTAL>>>();
    vq_epilogue<<<EPI_BLOCKS, 256>>>(X, CB, out);
    vq_finalize<<<1, 256>>>(out);
}